// round 16
// baseline (speedup 1.0000x reference)
#include <cuda_runtime.h>
#include <cuda_fp16.h>
#include <cfloat>

#define NN   50000
#define NE   800000
#define NEP  850000      // edges + self loops
#define HEADS 10
#define HID   10
#define CC    100        // HEADS*HID
#define NG    256
#define NOUT  10
#define NSLOPE 0.2f
#define GR   64          // gemm rows per block
#define KCH  32          // gemm k-chunk
#define TILE 32          // agg edges per smem tile

// ---------------- scratch (static device globals; zero-initialized) -----------
__device__ __half g_Ah[NN * CC];       // h in fp16 (aggregation gather)
__device__ float  g_B[NN * CC];        // layer input / aggregation output
__device__ int    g_SRC[NEP];
__device__ int    g_DST[NEP];
__device__ int    g_CSRC[NEP];         // CSR: src per position (sorted by dst)
__device__ int    g_CNT[NN];           // degree counts; re-zeroed each call after use
__device__ int    g_ROW[NN + 1];
__device__ int    g_WOFF[NN];
__device__ int    g_BATCH[NN];
__device__ float2 g_S2src[NN * HEADS]; // (s, exp(0.2*s))
__device__ float2 g_S2dst[NN * HEADS];
__device__ float  g_gsum[NG * CC];     // zeroed by k_convert each call
__device__ float  g_cnt[NG];

// ---- launch 1: convert edges+batch, degree count, zero gsum (is64 inline) ----
__global__ void k_convert(const void* ei, const void* bp) {
    __shared__ int s_is64;
    if (threadIdx.x == 0) {
        const long long* p = (const long long*)ei;
        int ok = 1;
#pragma unroll
        for (int q = 0; q < 16; q++) {
            long long v = p[q];
            if (v < 0 || v >= NN) ok = 0;
        }
        s_is64 = ok;
    }
    __syncthreads();
    int is64 = s_is64;
    int e = blockIdx.x * blockDim.x + threadIdx.x;
    if (e < NEP) {
        int s, d;
        if (e < NE) {
            if (is64) {
                const long long* p = (const long long*)ei;
                s = (int)p[e]; d = (int)p[NE + e];
            } else {
                const int* p = (const int*)ei;
                s = p[e]; d = p[NE + e];
            }
        } else {
            s = d = e - NE;   // self loop
        }
        g_SRC[e] = s;
        g_DST[e] = d;
        atomicAdd(&g_CNT[d], 1);
    }
    if (e < NN) {
        g_BATCH[e] = is64 ? (int)((const long long*)bp)[e] : ((const int*)bp)[e];
    }
    if (e < NG * CC) g_gsum[e] = 0.f;
}
// ---- launch 2: CSR scan + per-graph counts -----------------------------------
__global__ __launch_bounds__(1024) void k_scan() {
    __shared__ int wsum[32];
    __shared__ int s_carry;
    int tid = threadIdx.x;
    int lane = tid & 31, warp = tid >> 5;
    if (tid == 0) s_carry = 0;
    __syncthreads();
    for (int base = 0; base < NN; base += 1024) {
        int v = (base + tid < NN) ? g_CNT[base + tid] : 0;
        int x = v;
#pragma unroll
        for (int o = 1; o < 32; o <<= 1) {
            int y = __shfl_up_sync(~0u, x, o);
            if (lane >= o) x += y;
        }
        if (lane == 31) wsum[warp] = x;
        __syncthreads();
        if (warp == 0) {
            int w = wsum[lane];
#pragma unroll
            for (int o = 1; o < 32; o <<= 1) {
                int y = __shfl_up_sync(~0u, w, o);
                if (lane >= o) w += y;
            }
            wsum[lane] = w;
        }
        __syncthreads();
        int warpoff = (warp == 0) ? 0 : wsum[warp - 1];
        int ex = s_carry + warpoff + x - v;
        if (base + tid < NN) { g_ROW[base + tid] = ex; g_WOFF[base + tid] = ex; }
        __syncthreads();
        if (tid == 1023) s_carry += warpoff + x;
        __syncthreads();
    }
    if (tid == 0) g_ROW[NN] = s_carry;
    if (tid < NG) {
        int g = tid;
        int lo = 0, hi = NN;
        while (lo < hi) { int mid = (lo + hi) >> 1; if (g_BATCH[mid] < g) lo = mid + 1; else hi = mid; }
        int a = lo;
        lo = 0; hi = NN;
        while (lo < hi) { int mid = (lo + hi) >> 1; if (g_BATCH[mid] < g + 1) lo = mid + 1; else hi = mid; }
        g_cnt[g] = (float)(lo - a);
    }
}

// ---- launch 3 (L0) / 5,7 (L1,L2): gemm [+ scatter tail blocks on L0] ---------
__global__ __launch_bounds__(256) void k_gemm(const float* __restrict__ Xext,
                                              const float* __restrict__ W,
                                              const float* __restrict__ asrc,
                                              const float* __restrict__ adst,
                                              int Din, int use_gb, int gG) {
    if ((int)blockIdx.x >= gG) {
        // ---- scatter tail (CSR fill) + CNT re-zero for next call ----
        int e = (blockIdx.x - gG) * blockDim.x + threadIdx.x;
        if (e < NEP) {
            int d = g_DST[e];
            int pos = atomicAdd(&g_WOFF[d], 1);
            g_CSRC[pos] = g_SRC[e];
        }
        if (e < NN) g_CNT[e] = 0;
        return;
    }
    __shared__ float Wt[KCH * 128];      // 16KB; reused as 32x100 score stage
    __shared__ float Xs[KCH][GR + 4];    // 8.7KB
    const float* X = use_gb ? (const float*)g_B : Xext;
    int n0 = blockIdx.x * GR;
    int ct = threadIdx.x & 31;
    int rt = threadIdx.x >> 5;
    float acc[8][4];
#pragma unroll
    for (int i = 0; i < 8; i++)
#pragma unroll
        for (int j = 0; j < 4; j++) acc[i][j] = 0.f;

    for (int k0 = 0; k0 < Din; k0 += KCH) {
        int kk = min(KCH, Din - k0);
        for (int idx = threadIdx.x; idx < kk * 128; idx += 256) {
            int k = idx >> 7, c = idx & 127;
            Wt[idx] = (c < CC) ? W[(size_t)(k0 + k) * CC + c] : 0.f;
        }
        for (int idx = threadIdx.x; idx < GR * kk; idx += 256) {
            int r = idx / kk, k = idx - r * kk;
            int n = n0 + r;
            Xs[k][r] = (n < NN) ? X[(size_t)n * Din + k0 + k] : 0.f;
        }
        __syncthreads();
#pragma unroll 8
        for (int k = 0; k < kk; k++) {
            float4 w  = *(const float4*)&Wt[k * 128 + ct * 4];
            float4 xa = *(const float4*)&Xs[k][rt * 8];
            float4 xb = *(const float4*)&Xs[k][rt * 8 + 4];
            float xr[8] = {xa.x, xa.y, xa.z, xa.w, xb.x, xb.y, xb.z, xb.w};
            float wr[4] = {w.x, w.y, w.z, w.w};
#pragma unroll
            for (int i = 0; i < 8; i++)
#pragma unroll
                for (int j = 0; j < 4; j++) acc[i][j] += xr[i] * wr[j];
        }
        __syncthreads();
    }
    if (ct < 25) {
#pragma unroll
        for (int i = 0; i < 8; i++) {
            int n = n0 + rt * 8 + i;
            if (n < NN) {
                __half2* hp = (__half2*)&g_Ah[(size_t)n * CC + ct * 4];
                hp[0] = __floats2half2_rn(acc[i][0], acc[i][1]);
                hp[1] = __floats2half2_rn(acc[i][2], acc[i][3]);
            }
        }
    }
    float* stage = Wt;
#pragma unroll
    for (int half = 0; half < 2; half++) {
        __syncthreads();
        if (ct < 25 && (rt >> 2) == half) {
            int rl = (rt & 3) * 8;
#pragma unroll
            for (int i = 0; i < 8; i++) {
                stage[(rl + i) * CC + ct * 4 + 0] = acc[i][0];
                stage[(rl + i) * CC + ct * 4 + 1] = acc[i][1];
                stage[(rl + i) * CC + ct * 4 + 2] = acc[i][2];
                stage[(rl + i) * CC + ct * 4 + 3] = acc[i][3];
            }
        }
        __syncthreads();
        for (int idx = threadIdx.x; idx < 32 * HEADS; idx += 256) {
            int r = idx / HEADS, h = idx - r * HEADS;
            int n = n0 + half * 32 + r;
            if (n < NN) {
                float s1 = 0.f, s2 = 0.f;
#pragma unroll
                for (int f = 0; f < HID; f++) {
                    float v = stage[r * CC + h * HID + f];
                    s1 += v * asrc[h * HID + f];
                    s2 += v * adst[h * HID + f];
                }
                g_S2src[n * HEADS + h] = make_float2(s1, __expf(NSLOPE * s1));
                g_S2dst[n * HEADS + h] = make_float2(s2, __expf(NSLOPE * s2));
            }
        }
    }
}

// ---- launch 4 (CAPTURED): fused softmax + aggregation (block per dst) --------
// phase A: exv[h*32+j] head-major, shift/mask indexing, no div/mod, no ssrc smem.
// phase B: 25 quads x 4 parity groups, 4 cols/thread, 1 LDG.64 per edge.
__global__ __launch_bounds__(128) void k_agg(const float* __restrict__ bias) {
    int d = blockIdx.x;
    int t = threadIdx.x;
    __shared__ float  exv[HEADS * TILE];  // [h][j]
    __shared__ float2 sdst[HEADS];
    __shared__ float  red[3 * 150];       // 3 groups x 25 quads x 6 partials
    int row0 = g_ROW[d], row1 = g_ROW[d + 1];
    if (t < HEADS) sdst[t] = g_S2dst[d * HEADS + t];
    __syncthreads();

    // phase-B identity for this thread
    int grp = t / 25;                     // 0..3 edge-parity group (t<100)
    int q   = t - grp * 25;               // col quad 0..24 -> cols 4q..4q+3
    bool act = (t < 100);
    int hh01 = (4 * q + 1) / HID;         // head of cols 4q,4q+1
    int hh23 = (4 * q + 2) / HID;         // head of cols 4q+2,4q+3
    float ax0 = 0.f, ax1 = 0.f, ax2 = 0.f, ax3 = 0.f;
    float dn01 = 0.f, dn23 = 0.f;

    int jA = t & 31;                      // phase-A tile slot
    int hA = t >> 5;                      // base head (passes add 4)

    for (int t0 = row0; t0 < row1; t0 += TILE) {
        int nt = min(TILE, row1 - t0);
        // phase A: 3 passes (heads 0-3, 4-7, 8-9)
#pragma unroll
        for (int p = 0; p < 3; p++) {
            int h = p * 4 + hA;
            if (h < HEADS && jA < nt) {
                int s = __ldg(&g_CSRC[t0 + jA]);
                float2 S = g_S2src[s * HEADS + h];
                float2 D = sdst[h];
                float a  = S.x + D.x;
                float tt = S.y * D.y;      // e^{0.2(ss+sd)}
                float t2 = tt * tt;
                exv[h * TILE + jA] = (a >= 0.f) ? (t2 * t2 * tt) : tt;
            }
        }
        __syncthreads();
        // phase B: 4-way edge-parallel quad gather
        if (act) {
            for (int j = grp; j < nt; j += 4) {
                int s = __ldg(&g_CSRC[t0 + j]);
                float e01 = exv[hh01 * TILE + j];
                float e23 = exv[hh23 * TILE + j];
                uint2 hv = *(const uint2*)&g_Ah[(size_t)s * CC + 4 * q];
                float2 f01 = __half22float2(*(const __half2*)&hv.x);
                float2 f23 = __half22float2(*(const __half2*)&hv.y);
                ax0 += e01 * f01.x;
                ax1 += e01 * f01.y;
                ax2 += e23 * f23.x;
                ax3 += e23 * f23.y;
                dn01 += e01;
                dn23 += e23;
            }
        }
        __syncthreads();
    }
    if (act && grp > 0) {
        float* r = &red[(grp - 1) * 150 + q * 6];
        r[0] = ax0; r[1] = ax1; r[2] = ax2; r[3] = ax3; r[4] = dn01; r[5] = dn23;
    }
    __syncthreads();
    if (act && grp == 0) {
#pragma unroll
        for (int g = 0; g < 3; g++) {
            float* r = &red[g * 150 + q * 6];
            ax0 += r[0]; ax1 += r[1]; ax2 += r[2]; ax3 += r[3];
            dn01 += r[4]; dn23 += r[5];
        }
        float i01 = 1.f / dn01, i23 = 1.f / dn23;
        const float4 bv = *(const float4*)&bias[4 * q];
        float v0 = ax0 * i01 + bv.x;
        float v1 = ax1 * i01 + bv.y;
        float v2 = ax2 * i23 + bv.z;
        float v3 = ax3 * i23 + bv.w;
        v0 = v0 > 0.f ? v0 : 0.f;
        v1 = v1 > 0.f ? v1 : 0.f;
        v2 = v2 > 0.f ? v2 : 0.f;
        v3 = v3 > 0.f ? v3 : 0.f;
        *(float4*)&g_B[(size_t)d * CC + 4 * q] = make_float4(v0, v1, v2, v3);
    }
}

// ---------------- pooling -----------------------------------------------------
__global__ __launch_bounds__(128) void k_pool() {
    int c = threadIdx.x;
    if (c >= CC) return;
    int n0 = blockIdx.x * 256;
    if (n0 >= NN) return;
    int nend = min(n0 + 256, NN);
    int cur = g_BATCH[n0];
    float acc = 0.f;
    for (int n = n0; n < nend; n++) {
        int g = g_BATCH[n];
        if (g != cur) { atomicAdd(&g_gsum[cur * CC + c], acc); acc = 0.f; cur = g; }
        acc += g_B[(size_t)n * CC + c];
    }
    atomicAdd(&g_gsum[cur * CC + c], acc);
}

// ---------------- final FC ----------------------------------------------------
__global__ void k_fc(const float* __restrict__ Wfc, const float* __restrict__ bfc,
                     float* __restrict__ out) {
    int idx = blockIdx.x * blockDim.x + threadIdx.x;
    if (idx >= NG * NOUT) return;
    int g = idx / NOUT, o = idx - g * NOUT;
    float inv = 1.f / fmaxf(g_cnt[g], 1.f);
    float s = 0.f;
#pragma unroll 4
    for (int c = 0; c < CC; c++) s += g_gsum[g * CC + c] * Wfc[c * NOUT + o];
    out[idx] = s * inv + bfc[o];
}

// ---------------- driver ------------------------------------------------------
extern "C" void kernel_launch(void* const* d_in, const int* in_sizes, int n_in,
                              void* d_out, int out_size) {
    const float* x     = (const float*)d_in[0];
    const void*  ei    = d_in[1];
    const void*  batch = d_in[2];
    const float* W[3]    = { (const float*)d_in[3],  (const float*)d_in[7],  (const float*)d_in[11] };
    const float* asrc[3] = { (const float*)d_in[4],  (const float*)d_in[8],  (const float*)d_in[12] };
    const float* adst[3] = { (const float*)d_in[5],  (const float*)d_in[9],  (const float*)d_in[13] };
    const float* bb[3]   = { (const float*)d_in[6],  (const float*)d_in[10], (const float*)d_in[14] };
    const float* Wfc = (const float*)d_in[15];
    const float* bfc = (const float*)d_in[16];
    float* out = (float*)d_out;

    const int TB = 256;
    int gE = (NEP + TB - 1) / TB;
    int gG = (NN + GR - 1) / GR;

    // 1: convert, 2: scan, 3: gemm L0 + scatter tail, 4: agg L0 (capture slot)
    k_convert<<<gE, TB>>>(ei, batch);
    k_scan<<<1, 1024>>>();

    for (int l = 0; l < 3; l++) {
        int Din = (l == 0) ? 128 : CC;
        int grid = (l == 0) ? (gG + gE) : gG;   // L0 carries scatter tail blocks
        k_gemm<<<grid, 256>>>(x, W[l], asrc[l], adst[l], Din, l > 0 ? 1 : 0, gG);
        k_agg<<<NN, 128>>>(bb[l]);
    }

    k_pool<<<(NN + 255) / 256, 128>>>();
    k_fc<<<(NG * NOUT + TB - 1) / TB, TB>>>(Wfc, bfc, out);
}

// round 17
// speedup vs baseline: 1.1756x; 1.1756x over previous
#include <cuda_runtime.h>
#include <cuda_fp16.h>
#include <cfloat>

#define NN   50000
#define NE   800000
#define NEP  850000      // edges + self loops
#define HEADS 10
#define HID   10
#define CC    100        // HEADS*HID
#define NG    256
#define NOUT  10
#define NSLOPE 0.2f
#define GR   64          // gemm rows per block
#define KCH  32          // gemm k-chunk
#define TILE 32          // agg edges per smem tile

// ---------------- scratch (static device globals; zero-initialized) -----------
__device__ __half g_Ah[NN * CC];       // h in fp16 (aggregation gather)
__device__ float  g_B[NN * CC];        // layer input / aggregation output
__device__ int    g_SRC[NEP];
__device__ int    g_DST[NEP];
__device__ int    g_CSRC[NEP];         // CSR: src per position (sorted by dst)
__device__ int    g_CNT[NN];           // degree counts; re-zeroed each call after use
__device__ int    g_ROW[NN + 1];
__device__ int    g_WOFF[NN];
__device__ int    g_BATCH[NN];
__device__ float2 g_S2src[NN * HEADS]; // (s, exp(0.2*s))
__device__ float2 g_S2dst[NN * HEADS];
__device__ float  g_gsum[NG * CC];     // zeroed by k_convert each call
__device__ float  g_cnt[NG];

// ---- launch 1: convert edges+batch, degree count, zero gsum (is64 inline) ----
__global__ void k_convert(const void* ei, const void* bp) {
    __shared__ int s_is64;
    if (threadIdx.x == 0) {
        const long long* p = (const long long*)ei;
        int ok = 1;
#pragma unroll
        for (int q = 0; q < 16; q++) {
            long long v = p[q];
            if (v < 0 || v >= NN) ok = 0;
        }
        s_is64 = ok;
    }
    __syncthreads();
    int is64 = s_is64;
    int e = blockIdx.x * blockDim.x + threadIdx.x;
    if (e < NEP) {
        int s, d;
        if (e < NE) {
            if (is64) {
                const long long* p = (const long long*)ei;
                s = (int)p[e]; d = (int)p[NE + e];
            } else {
                const int* p = (const int*)ei;
                s = p[e]; d = p[NE + e];
            }
        } else {
            s = d = e - NE;   // self loop
        }
        g_SRC[e] = s;
        g_DST[e] = d;
        atomicAdd(&g_CNT[d], 1);
    }
    if (e < NN) {
        g_BATCH[e] = is64 ? (int)((const long long*)bp)[e] : ((const int*)bp)[e];
    }
    if (e < NG * CC) g_gsum[e] = 0.f;
}
// ---- launch 2: CSR scan + per-graph counts -----------------------------------
__global__ __launch_bounds__(1024) void k_scan() {
    __shared__ int wsum[32];
    __shared__ int s_carry;
    int tid = threadIdx.x;
    int lane = tid & 31, warp = tid >> 5;
    if (tid == 0) s_carry = 0;
    __syncthreads();
    for (int base = 0; base < NN; base += 1024) {
        int v = (base + tid < NN) ? g_CNT[base + tid] : 0;
        int x = v;
#pragma unroll
        for (int o = 1; o < 32; o <<= 1) {
            int y = __shfl_up_sync(~0u, x, o);
            if (lane >= o) x += y;
        }
        if (lane == 31) wsum[warp] = x;
        __syncthreads();
        if (warp == 0) {
            int w = wsum[lane];
#pragma unroll
            for (int o = 1; o < 32; o <<= 1) {
                int y = __shfl_up_sync(~0u, w, o);
                if (lane >= o) w += y;
            }
            wsum[lane] = w;
        }
        __syncthreads();
        int warpoff = (warp == 0) ? 0 : wsum[warp - 1];
        int ex = s_carry + warpoff + x - v;
        if (base + tid < NN) { g_ROW[base + tid] = ex; g_WOFF[base + tid] = ex; }
        __syncthreads();
        if (tid == 1023) s_carry += warpoff + x;
        __syncthreads();
    }
    if (tid == 0) g_ROW[NN] = s_carry;
    if (tid < NG) {
        int g = tid;
        int lo = 0, hi = NN;
        while (lo < hi) { int mid = (lo + hi) >> 1; if (g_BATCH[mid] < g) lo = mid + 1; else hi = mid; }
        int a = lo;
        lo = 0; hi = NN;
        while (lo < hi) { int mid = (lo + hi) >> 1; if (g_BATCH[mid] < g + 1) lo = mid + 1; else hi = mid; }
        g_cnt[g] = (float)(lo - a);
    }
}

// ---- launch 3 (L0) / 5,7 (L1,L2): gemm [+ scatter tail blocks on L0] ---------
__global__ __launch_bounds__(256) void k_gemm(const float* __restrict__ Xext,
                                              const float* __restrict__ W,
                                              const float* __restrict__ asrc,
                                              const float* __restrict__ adst,
                                              int Din, int use_gb, int gG) {
    if ((int)blockIdx.x >= gG) {
        int e = (blockIdx.x - gG) * blockDim.x + threadIdx.x;
        if (e < NEP) {
            int d = g_DST[e];
            int pos = atomicAdd(&g_WOFF[d], 1);
            g_CSRC[pos] = g_SRC[e];
        }
        if (e < NN) g_CNT[e] = 0;
        return;
    }
    __shared__ float Wt[KCH * 128];      // 16KB; reused as 32x100 score stage
    __shared__ float Xs[KCH][GR + 4];    // 8.7KB
    const float* X = use_gb ? (const float*)g_B : Xext;
    int n0 = blockIdx.x * GR;
    int ct = threadIdx.x & 31;
    int rt = threadIdx.x >> 5;
    float acc[8][4];
#pragma unroll
    for (int i = 0; i < 8; i++)
#pragma unroll
        for (int j = 0; j < 4; j++) acc[i][j] = 0.f;

    for (int k0 = 0; k0 < Din; k0 += KCH) {
        int kk = min(KCH, Din - k0);
        for (int idx = threadIdx.x; idx < kk * 128; idx += 256) {
            int k = idx >> 7, c = idx & 127;
            Wt[idx] = (c < CC) ? W[(size_t)(k0 + k) * CC + c] : 0.f;
        }
        for (int idx = threadIdx.x; idx < GR * kk; idx += 256) {
            int r = idx / kk, k = idx - r * kk;
            int n = n0 + r;
            Xs[k][r] = (n < NN) ? X[(size_t)n * Din + k0 + k] : 0.f;
        }
        __syncthreads();
#pragma unroll 8
        for (int k = 0; k < kk; k++) {
            float4 w  = *(const float4*)&Wt[k * 128 + ct * 4];
            float4 xa = *(const float4*)&Xs[k][rt * 8];
            float4 xb = *(const float4*)&Xs[k][rt * 8 + 4];
            float xr[8] = {xa.x, xa.y, xa.z, xa.w, xb.x, xb.y, xb.z, xb.w};
            float wr[4] = {w.x, w.y, w.z, w.w};
#pragma unroll
            for (int i = 0; i < 8; i++)
#pragma unroll
                for (int j = 0; j < 4; j++) acc[i][j] += xr[i] * wr[j];
        }
        __syncthreads();
    }
    if (ct < 25) {
#pragma unroll
        for (int i = 0; i < 8; i++) {
            int n = n0 + rt * 8 + i;
            if (n < NN) {
                __half2* hp = (__half2*)&g_Ah[(size_t)n * CC + ct * 4];
                hp[0] = __floats2half2_rn(acc[i][0], acc[i][1]);
                hp[1] = __floats2half2_rn(acc[i][2], acc[i][3]);
            }
        }
    }
    float* stage = Wt;
#pragma unroll
    for (int half = 0; half < 2; half++) {
        __syncthreads();
        if (ct < 25 && (rt >> 2) == half) {
            int rl = (rt & 3) * 8;
#pragma unroll
            for (int i = 0; i < 8; i++) {
                stage[(rl + i) * CC + ct * 4 + 0] = acc[i][0];
                stage[(rl + i) * CC + ct * 4 + 1] = acc[i][1];
                stage[(rl + i) * CC + ct * 4 + 2] = acc[i][2];
                stage[(rl + i) * CC + ct * 4 + 3] = acc[i][3];
            }
        }
        __syncthreads();
        for (int idx = threadIdx.x; idx < 32 * HEADS; idx += 256) {
            int r = idx / HEADS, h = idx - r * HEADS;
            int n = n0 + half * 32 + r;
            if (n < NN) {
                float s1 = 0.f, s2 = 0.f;
#pragma unroll
                for (int f = 0; f < HID; f++) {
                    float v = stage[r * CC + h * HID + f];
                    s1 += v * asrc[h * HID + f];
                    s2 += v * adst[h * HID + f];
                }
                g_S2src[n * HEADS + h] = make_float2(s1, __expf(NSLOPE * s1));
                g_S2dst[n * HEADS + h] = make_float2(s2, __expf(NSLOPE * s2));
            }
        }
    }
}

// ---- launch 4 (CAPTURED): fused softmax + aggregation (block per dst) --------
// R14 structure + ssrc preload (1 global load/edge) + shift/mask phase A.
__global__ __launch_bounds__(128) void k_agg(const float* __restrict__ bias) {
    int d = blockIdx.x;
    int t = threadIdx.x;
    __shared__ float  exv[TILE * HEADS]; // [j][h] edge-major (phase B layout of R14)
    __shared__ int    ssrc[TILE];
    __shared__ float2 sdst[HEADS];
    __shared__ float  red[3 * 50];
    int row0 = g_ROW[d], row1 = g_ROW[d + 1];
    if (t < HEADS) sdst[t] = g_S2dst[d * HEADS + t];
    __syncthreads();
    bool lo = (t < 50);
    bool hi = (t >= 64 && t < 114);
    int cp = lo ? t : (t - 64);
    int hh = cp / 5;
    int jA = t & 31;                     // phase-A edge slot
    int hA = t >> 5;                     // phase-A base head
    float ax = 0.f, ay = 0.f, dn = 0.f;
    for (int t0 = row0; t0 < row1; t0 += TILE) {
        int nt = min(TILE, row1 - t0);
        // preload: one global index load per edge
        if (t < nt) ssrc[t] = g_CSRC[t0 + t];
        __syncthreads();
        // phase A: heads via shift/mask, src via smem
#pragma unroll
        for (int p = 0; p < 3; p++) {
            int h = hA + (p << 2);
            if (h < HEADS && jA < nt) {
                int s = ssrc[jA];
                float2 S = g_S2src[s * HEADS + h];
                float2 D = sdst[h];
                float a  = S.x + D.x;
                float tt = S.y * D.y;    // e^{0.2(ss+sd)}
                float t2 = tt * tt;
                exv[jA * HEADS + h] = (a >= 0.f) ? (t2 * t2 * tt) : tt;
            }
        }
        __syncthreads();
        // phase B: weighted gather, 2-way edge-parallel (R14 proven)
        if (lo || hi) {
            for (int j = lo ? 0 : 1; j < nt; j += 2) {
                int s = ssrc[j];
                float ex = exv[j * HEADS + hh];
                __half2 hv = *(const __half2*)&g_Ah[(size_t)s * CC + 2 * cp];
                float2 f = __half22float2(hv);
                ax += ex * f.x;
                ay += ex * f.y;
                dn += ex;
            }
        }
        __syncthreads();
    }
    if (hi) { red[cp] = ax; red[50 + cp] = ay; red[100 + cp] = dn; }
    __syncthreads();
    if (lo) {
        ax += red[cp];
        ay += red[50 + cp];
        dn += red[100 + cp];
        float invd = 1.f / dn;
        float vx = ax * invd + bias[2 * cp];
        float vy = ay * invd + bias[2 * cp + 1];
        vx = vx > 0.f ? vx : 0.f;
        vy = vy > 0.f ? vy : 0.f;
        *(float2*)&g_B[(size_t)d * CC + 2 * cp] = make_float2(vx, vy);
    }
}

// ---------------- pooling -----------------------------------------------------
__global__ __launch_bounds__(128) void k_pool() {
    int c = threadIdx.x;
    if (c >= CC) return;
    int n0 = blockIdx.x * 256;
    if (n0 >= NN) return;
    int nend = min(n0 + 256, NN);
    int cur = g_BATCH[n0];
    float acc = 0.f;
    for (int n = n0; n < nend; n++) {
        int g = g_BATCH[n];
        if (g != cur) { atomicAdd(&g_gsum[cur * CC + c], acc); acc = 0.f; cur = g; }
        acc += g_B[(size_t)n * CC + c];
    }
    atomicAdd(&g_gsum[cur * CC + c], acc);
}

// ---------------- final FC ----------------------------------------------------
__global__ void k_fc(const float* __restrict__ Wfc, const float* __restrict__ bfc,
                     float* __restrict__ out) {
    int idx = blockIdx.x * blockDim.x + threadIdx.x;
    if (idx >= NG * NOUT) return;
    int g = idx / NOUT, o = idx - g * NOUT;
    float inv = 1.f / fmaxf(g_cnt[g], 1.f);
    float s = 0.f;
#pragma unroll 4
    for (int c = 0; c < CC; c++) s += g_gsum[g * CC + c] * Wfc[c * NOUT + o];
    out[idx] = s * inv + bfc[o];
}

// ---------------- driver ------------------------------------------------------
extern "C" void kernel_launch(void* const* d_in, const int* in_sizes, int n_in,
                              void* d_out, int out_size) {
    const float* x     = (const float*)d_in[0];
    const void*  ei    = d_in[1];
    const void*  batch = d_in[2];
    const float* W[3]    = { (const float*)d_in[3],  (const float*)d_in[7],  (const float*)d_in[11] };
    const float* asrc[3] = { (const float*)d_in[4],  (const float*)d_in[8],  (const float*)d_in[12] };
    const float* adst[3] = { (const float*)d_in[5],  (const float*)d_in[9],  (const float*)d_in[13] };
    const float* bb[3]   = { (const float*)d_in[6],  (const float*)d_in[10], (const float*)d_in[14] };
    const float* Wfc = (const float*)d_in[15];
    const float* bfc = (const float*)d_in[16];
    float* out = (float*)d_out;

    const int TB = 256;
    int gE = (NEP + TB - 1) / TB;
    int gG = (NN + GR - 1) / GR;

    // 1: convert, 2: scan, 3: gemm L0 + scatter tail, 4: agg L0 (capture slot)
    k_convert<<<gE, TB>>>(ei, batch);
    k_scan<<<1, 1024>>>();

    for (int l = 0; l < 3; l++) {
        int Din = (l == 0) ? 128 : CC;
        int grid = (l == 0) ? (gG + gE) : gG;   // L0 carries scatter tail blocks
        k_gemm<<<grid, 256>>>(x, W[l], asrc[l], adst[l], Din, l > 0 ? 1 : 0, gG);
        k_agg<<<NN, 128>>>(bb[l]);
    }

    k_pool<<<(NN + 255) / 256, 128>>>();
    k_fc<<<(NG * NOUT + TB - 1) / TB, TB>>>(Wfc, bfc, out);
}